// round 14
// baseline (speedup 1.0000x reference)
#include <cuda_runtime.h>

#define FULLMASK 0xFFFFFFFFu
#define NEAR_T 0.1f
#define FAR_T  3.0f
#define LOG2E  1.4426950408889634f

// scratch: up to 32768 rays x 4 quarters x {r,g,b,T} floats = 2 MB
__device__ float g_partial[32768 * 16];
// dynamic task counter + grid-barrier counters (zero-init; self-resetting)
__device__ unsigned int g_counter;
__device__ unsigned int g_done;
__device__ unsigned int g_exit;

__device__ __forceinline__ float ex2_approx(float x) {
    float r;
    asm("ex2.approx.f32 %0, %1;" : "=f"(r) : "f"(x));
    return r;
}
__device__ __forceinline__ float rcp_approx(float x) {
    float r;
    asm("rcp.approx.f32 %0, %1;" : "=f"(r) : "f"(x));
    return r;
}

// Inner sample loop, specialized on per-task axis activity (proved by ballot).
// Inactive axis => frac==0 for every sample => its +corner loads/lerps are
// dead and removed at compile time. bk is pre-scaled by log2(e) so the
// sigmoid exp is a single ex2.approx.
template<bool AX, bool AY, bool AZ>
__device__ __forceinline__ float run_quarter(
    const float* __restrict__ shp, bool shlane, int p8src, float bk,
    int len, int codel, float frxl, float fryl, float frzl, float wlane)
{
    float accR = 0.0f;

    #pragma unroll 4
    for (int j = 0; j < len; ++j) {
        // broadcast sample-j data from lane j
        const int   cs  = __shfl_sync(FULLMASK, codel, j);
        const float w   = __shfl_sync(FULLMASK, wlane, j);
        const float frx = AX ? __shfl_sync(FULLMASK, frxl, j) : 0.0f;
        const float fry = AY ? __shfl_sync(FULLMASK, fryl, j) : 0.0f;
        const float frz = AZ ? __shfl_sync(FULLMASK, frzl, j) : 0.0f;

        const int O  = cs & 0x03FFFFFF;                       // a00 * 27
        const int Dz = (AZ && (cs & (1 << 26))) ? 27 : 0;
        const int Dy = (AY && (cs & (1 << 27))) ? (27 << 7)  : 0;
        const int Dx = (AX && (cs & (1 << 28))) ? (27 << 14) : 0;

        float v000 = 0.f, v001 = 0.f, v010 = 0.f, v011 = 0.f;
        float v100 = 0.f, v101 = 0.f, v110 = 0.f, v111 = 0.f;
        if (shlane) {
            v000 = __ldg(shp + O);
            if (AZ) v001 = __ldg(shp + O + Dz);
            if (AY) {
                v010 = __ldg(shp + O + Dy);
                if (AZ) v011 = __ldg(shp + O + Dy + Dz);
            }
            if (AX) {
                v100 = __ldg(shp + O + Dx);
                if (AZ) v101 = __ldg(shp + O + Dx + Dz);
                if (AY) {
                    v110 = __ldg(shp + O + Dx + Dy);
                    if (AZ) v111 = __ldg(shp + O + Dx + Dy + Dz);
                }
            }
        }

        // trilerp with dead axes folded away
        const float z00 = AZ ? fmaf(frz, v001 - v000, v000) : v000;
        const float z01 = AY ? (AZ ? fmaf(frz, v011 - v010, v010) : v010) : 0.0f;
        const float z10 = AX ? (AZ ? fmaf(frz, v101 - v100, v100) : v100) : 0.0f;
        const float z11 = (AX && AY) ? (AZ ? fmaf(frz, v111 - v110, v110) : v110) : 0.0f;
        const float y0  = AY ? fmaf(fry, z01 - z00, z00) : z00;
        const float y1  = AX ? (AY ? fmaf(fry, z11 - z10, z10) : z10) : 0.0f;
        const float acc = AX ? fmaf(frx, y1 - y0, y0) : y0;

        // per-channel dot with (log2e-scaled) basis over 9 lanes
        float p = acc * bk;
        const float p8 = __shfl_sync(FULLMASK, p, p8src);
        p += __shfl_down_sync(FULLMASK, p, 4);
        p += __shfl_down_sync(FULLMASK, p, 2);
        p += __shfl_down_sync(FULLMASK, p, 1);
        p += p8;   // full channel sum (x log2e) valid at lanes 0, 9, 18

        // sigmoid: 1/(1 + 2^-p)  (p pre-scaled by log2e)
        const float e   = ex2_approx(-p);
        const float rgb = rcp_approx(1.0f + e);

        accR = fmaf(w, rgb, accR);
    }
    return accR;
}

__global__ __launch_bounds__(256, 6)
void plen_fused(const float* __restrict__ dens,
                const float* __restrict__ sh,
                const float* __restrict__ rayo,
                const float* __restrict__ rayd,
                const int*   __restrict__ nsamp,
                float*       __restrict__ out,
                int num_rays)
{
    const int lane = threadIdx.x & 31;

    const int S = nsamp ? *nsamp : 128;
    const float delta = (FAR_T - NEAR_T) / (float)max(S - 1, 1);
    const int L = (S + 3) >> 2;              // samples per quarter-task (32 when S=128)

    // Lane roles for the SH gather: lanes 0..26 -> coeff (c=lane/9, k=lane%9).
    const int  c      = lane / 9;
    const int  k      = lane - c * 9;
    const bool shlane = (lane < 27);
    const int  p8src  = shlane ? (c * 9 + 8) : 31;
    const float* shp  = sh + lane;

    const int ntask = num_rays << 2;

    for (;;) {
        // dynamic task fetch (lane 0 pulls, broadcast)
        unsigned int t = 0;
        if (lane == 0) t = atomicAdd(&g_counter, 1u);
        t = __shfl_sync(FULLMASK, t, 0);
        if (t >= (unsigned)ntask) break;
        const int task = (int)t;

        const int ray = task >> 2;
        const int q   = task & 3;
        const int s0  = q * L;
        const int len = min(S, s0 + L) - s0;

        const float ox = __ldg(rayo + ray * 3 + 0);
        const float oy = __ldg(rayo + ray * 3 + 1);
        const float oz = __ldg(rayo + ray * 3 + 2);
        const float dx = __ldg(rayd + ray * 3 + 0);
        const float dy = __ldg(rayd + ray * 3 + 1);
        const float dz = __ldg(rayd + ray * 3 + 2);

        // degree-2 SH basis value for this lane's k, pre-scaled by log2(e)
        float nx = dx, ny = dy, nz = dz;
        float ssq = nx * nx + ny * ny + nz * nz;
        if (ssq < 1e-8f) { nx = 0.0f; ny = 0.0f; nz = 1.0f; ssq = 1.0f; }
        const float invn = rsqrtf(ssq);
        nx *= invn; ny *= invn; nz *= invn;
        float bk;
        switch (k) {
            case 0:  bk = 0.282095f; break;
            case 1:  bk = 0.488603f * ny; break;
            case 2:  bk = 0.488603f * nz; break;
            case 3:  bk = 0.488603f * nx; break;
            case 4:  bk = 1.092548f * nx * ny; break;
            case 5:  bk = 1.092548f * ny * nz; break;
            case 6:  bk = 0.315392f * (3.0f * nz * nz - 1.0f); break;
            case 7:  bk = 1.092548f * nx * nz; break;
            default: bk = 0.546274f * (nx * nx - ny * ny); break;
        }
        bk *= LOG2E;

        // voxel position p(s) = base + s*step  (scene [-1,1]^3, dims=127 -> *63.5)
        const float bx  = fmaf(NEAR_T * 63.5f, dx, (ox + 1.0f) * 63.5f);
        const float by  = fmaf(NEAR_T * 63.5f, dy, (oy + 1.0f) * 63.5f);
        const float bz  = fmaf(NEAR_T * 63.5f, dz, (oz + 1.0f) * 63.5f);
        const float stx = dx * (63.5f * delta);
        const float sty = dy * (63.5f * delta);
        const float stz = dz * (63.5f * delta);

        // ---- per-lane coordinate precompute: lane l owns sample s0+l ----
        const float sfl = (float)(s0 + lane);
        const float px = fmaf(sfl, stx, bx);
        const float py = fmaf(sfl, sty, by);
        const float pz = fmaf(sfl, stz, bz);
        const float pcx = fminf(fmaxf(px, 0.0f), 127.0f);
        const float pcy = fminf(fmaxf(py, 0.0f), 127.0f);
        const float pcz = fminf(fmaxf(pz, 0.0f), 127.0f);
        const float fxq = floorf(pcx), fyq = floorf(pcy), fzq = floorf(pcz);
        const float frxl = pcx - fxq, fryl = pcy - fyq, frzl = pcz - fzq;
        const int ix0 = (int)fxq, iy0 = (int)fyq, iz0 = (int)fzq;
        // frac==0 => +corner is multiplicatively dead => collapse its address
        const int dxb = (frxl > 0.0f) ? 1 : 0;
        const int dyb = (fryl > 0.0f) ? 1 : 0;
        const int dzb = (frzl > 0.0f) ? 1 : 0;
        const int a00l  = (ix0 << 14) + (iy0 << 7) + iz0;
        // pack a00*27 (< 2^26) + axis flags into one broadcast word
        const int codel = a00l * 27 | (dzb << 26) | (dyb << 27) | (dxb << 28);

        // ---- per-lane density trilerp for own sample (amortized over 32) ----
        const int Od  = a00l;
        const int DzD = dzb;
        const int DyD = dyb << 7;
        const int DxD = dxb << 14;
        const int OyD  = Od + DyD;
        const int OxD  = Od + DxD;
        const int OxyD = OxD + DyD;
        const float d000 = __ldg(dens + Od);
        const float d001 = __ldg(dens + Od  + DzD);
        const float d010 = __ldg(dens + OyD);
        const float d011 = __ldg(dens + OyD + DzD);
        const float d100 = __ldg(dens + OxD);
        const float d101 = __ldg(dens + OxD + DzD);
        const float d110 = __ldg(dens + OxyD);
        const float d111 = __ldg(dens + OxyD + DzD);
        const float z00d = fmaf(frzl, d001 - d000, d000);
        const float z01d = fmaf(frzl, d011 - d010, d010);
        const float z10d = fmaf(frzl, d101 - d100, d100);
        const float z11d = fmaf(frzl, d111 - d110, d110);
        const float y0d  = fmaf(fryl, z01d - z00d, z00d);
        const float y1d  = fmaf(fryl, z11d - z10d, z10d);
        float sig = fmaf(frxl, y1d - y0d, y0d);
        sig = fmaxf(sig, 0.0f);
        const float am1 = __expf(-sig * delta);       // 1 - alpha
        // inclusive scan-product of v = (1-alpha+1e-10) across lanes
        float P = am1 + 1e-10f;
        #pragma unroll
        for (int off = 1; off < 32; off <<= 1) {
            const float tprev = __shfl_up_sync(FULLMASK, P, off);
            if (lane >= off) P *= tprev;
        }
        float Tj = __shfl_up_sync(FULLMASK, P, 1);    // exclusive transmittance
        if (lane == 0) Tj = 1.0f;
        const float wlane = Tj * (1.0f - am1);
        const float Tout  = __shfl_sync(FULLMASK, P, len - 1);

        // ---- task-level axis-activity vote (only lanes owning real samples) ----
        const bool valid = lane < len;
        const unsigned bxv = __ballot_sync(FULLMASK, dxb && valid);
        const unsigned byv = __ballot_sync(FULLMASK, dyb && valid);
        const unsigned bzv = __ballot_sync(FULLMASK, dzb && valid);
        const int m = ((bxv ? 4 : 0) | (byv ? 2 : 0) | (bzv ? 1 : 0));

        float accR;
        switch (m) {
            case 0: accR = run_quarter<false,false,false>(shp, shlane, p8src, bk, len, codel, frxl, fryl, frzl, wlane); break;
            case 1: accR = run_quarter<false,false,true >(shp, shlane, p8src, bk, len, codel, frxl, fryl, frzl, wlane); break;
            case 2: accR = run_quarter<false,true ,false>(shp, shlane, p8src, bk, len, codel, frxl, fryl, frzl, wlane); break;
            case 3: accR = run_quarter<false,true ,true >(shp, shlane, p8src, bk, len, codel, frxl, fryl, frzl, wlane); break;
            case 4: accR = run_quarter<true ,false,false>(shp, shlane, p8src, bk, len, codel, frxl, fryl, frzl, wlane); break;
            case 5: accR = run_quarter<true ,false,true >(shp, shlane, p8src, bk, len, codel, frxl, fryl, frzl, wlane); break;
            case 6: accR = run_quarter<true ,true ,false>(shp, shlane, p8src, bk, len, codel, frxl, fryl, frzl, wlane); break;
            default:accR = run_quarter<true ,true ,true >(shp, shlane, p8src, bk, len, codel, frxl, fryl, frzl, wlane); break;
        }

        // emit quarter partials: {r,g,b} at lanes 0/9/18, quarter T at lane 0
        float* dst = g_partial + (task << 2);
        if (shlane && k == 0) dst[c] = accR;
        if (lane == 0)        dst[3] = Tout;
    }

    // ================= software grid barrier =================
    // All 888 CTAs are resident (grid == 148 SMs x 6 CTAs, regs capped by
    // launch_bounds), so spinning is deadlock-free.
    __syncthreads();
    if (threadIdx.x == 0) {
        __threadfence();                      // make partials visible
        atomicAdd(&g_done, 1u);
        volatile unsigned int* dd = &g_done;
        while (*dd < gridDim.x) { }
        __threadfence();                      // acquire partials
    }
    __syncthreads();

    // ================= combine (former pass2) =================
    const int tid = blockIdx.x * blockDim.x + threadIdx.x;
    if (tid < num_rays) {
        const float4* p4 = (const float4*)(g_partial + (tid << 4));
        const float4 q0 = p4[0], q1 = p4[1], q2 = p4[2], q3 = p4[3];
        float T = 1.0f, o0 = 0.0f, o1 = 0.0f, o2 = 0.0f;
        o0 = fmaf(T, q0.x, o0); o1 = fmaf(T, q0.y, o1); o2 = fmaf(T, q0.z, o2); T *= q0.w;
        o0 = fmaf(T, q1.x, o0); o1 = fmaf(T, q1.y, o1); o2 = fmaf(T, q1.z, o2); T *= q1.w;
        o0 = fmaf(T, q2.x, o0); o1 = fmaf(T, q2.y, o1); o2 = fmaf(T, q2.z, o2); T *= q2.w;
        o0 = fmaf(T, q3.x, o0); o1 = fmaf(T, q3.y, o1); o2 = fmaf(T, q3.z, o2); T *= q3.w;
        out[tid * 3 + 0] = o0;
        out[tid * 3 + 1] = o1;
        out[tid * 3 + 2] = o2;
    }

    // ================= counter reset for next graph replay =================
    __syncthreads();
    if (threadIdx.x == 0) {
        __threadfence();
        const unsigned int e = atomicAdd(&g_exit, 1u);
        if (e == gridDim.x - 1) {
            // last CTA out: everyone else is past the spin and combine
            g_counter = 0;
            g_done    = 0;
            g_exit    = 0;
            __threadfence();
        }
    }
}

extern "C" void kernel_launch(void* const* d_in, const int* in_sizes, int n_in,
                              void* d_out, int out_size)
{
    const float* dens = (const float*)d_in[0];
    const float* sh   = (const float*)d_in[1];
    const float* ro   = (const float*)d_in[2];
    const float* rd   = (const float*)d_in[3];
    const int*   ns   = (n_in >= 5) ? (const int*)d_in[4] : nullptr;
    float* out = (float*)d_out;

    const int num_rays = in_sizes[2] / 3;

    const int grid1 = 888;   // 148 SMs x 6 CTAs of 256 -> fully resident, persistent
    plen_fused<<<grid1, 256>>>(dens, sh, ro, rd, ns, out, num_rays);
}

// round 15
// speedup vs baseline: 1.1865x; 1.1865x over previous
#include <cuda_runtime.h>

#define FULLMASK 0xFFFFFFFFu
#define NEAR_T 0.1f
#define FAR_T  3.0f
#define LOG2E  1.4426950408889634f

// scratch: up to 32768 rays x 4 quarters x {r,g,b,T} floats = 2 MB
__device__ float g_partial[32768 * 16];
// dynamic task counter (zero-initialized; reset by pass2 for graph replays)
__device__ unsigned int g_counter;

__device__ __forceinline__ float ex2_approx(float x) {
    float r;
    asm("ex2.approx.f32 %0, %1;" : "=f"(r) : "f"(x));
    return r;
}
__device__ __forceinline__ float rcp_approx(float x) {
    float r;
    asm("rcp.approx.f32 %0, %1;" : "=f"(r) : "f"(x));
    return r;
}

// Inner sample loop, specialized on per-task axis activity (proved by ballot).
// Inactive axis => frac==0 for every sample => its +corner loads/lerps are
// dead and removed at compile time. bk is pre-scaled by -log2(e); the loop
// only reduces q = -log2e*dot and stores it (head lanes) to smem — the
// sigmoid + weighting + sample-sum happen once per task after the loop.
template<bool AX, bool AY, bool AZ>
__device__ __forceinline__ void run_quarter(
    const float* __restrict__ shp, bool shlane, bool headlane, int p8src,
    float bk, int len, int codel, float frxl, float fryl, float frzl,
    float* __restrict__ spc)
{
    #pragma unroll 4
    for (int j = 0; j < len; ++j) {
        // broadcast sample-j data from lane j
        const int   cs  = __shfl_sync(FULLMASK, codel, j);
        const float frx = AX ? __shfl_sync(FULLMASK, frxl, j) : 0.0f;
        const float fry = AY ? __shfl_sync(FULLMASK, fryl, j) : 0.0f;
        const float frz = AZ ? __shfl_sync(FULLMASK, frzl, j) : 0.0f;

        const int O  = cs & 0x03FFFFFF;                       // a00 * 27
        const int Dz = (AZ && (cs & (1 << 26))) ? 27 : 0;
        const int Dy = (AY && (cs & (1 << 27))) ? (27 << 7)  : 0;
        const int Dx = (AX && (cs & (1 << 28))) ? (27 << 14) : 0;

        float v000 = 0.f, v001 = 0.f, v010 = 0.f, v011 = 0.f;
        float v100 = 0.f, v101 = 0.f, v110 = 0.f, v111 = 0.f;
        if (shlane) {
            v000 = __ldg(shp + O);
            if (AZ) v001 = __ldg(shp + O + Dz);
            if (AY) {
                v010 = __ldg(shp + O + Dy);
                if (AZ) v011 = __ldg(shp + O + Dy + Dz);
            }
            if (AX) {
                v100 = __ldg(shp + O + Dx);
                if (AZ) v101 = __ldg(shp + O + Dx + Dz);
                if (AY) {
                    v110 = __ldg(shp + O + Dx + Dy);
                    if (AZ) v111 = __ldg(shp + O + Dx + Dy + Dz);
                }
            }
        }

        // trilerp with dead axes folded away
        const float z00 = AZ ? fmaf(frz, v001 - v000, v000) : v000;
        const float z01 = AY ? (AZ ? fmaf(frz, v011 - v010, v010) : v010) : 0.0f;
        const float z10 = AX ? (AZ ? fmaf(frz, v101 - v100, v100) : v100) : 0.0f;
        const float z11 = (AX && AY) ? (AZ ? fmaf(frz, v111 - v110, v110) : v110) : 0.0f;
        const float y0  = AY ? fmaf(fry, z01 - z00, z00) : z00;
        const float y1  = AX ? (AY ? fmaf(fry, z11 - z10, z10) : z10) : 0.0f;
        const float acc = AX ? fmaf(frx, y1 - y0, y0) : y0;

        // per-channel dot with (-log2e scaled) basis over 9 lanes
        float p = acc * bk;
        const float p8 = __shfl_sync(FULLMASK, p, p8src);
        p += __shfl_down_sync(FULLMASK, p, 4);
        p += __shfl_down_sync(FULLMASK, p, 2);
        p += __shfl_down_sync(FULLMASK, p, 1);
        p += p8;   // full channel q valid at lanes 0, 9, 18

        if (headlane) spc[j] = p;   // predicated STS, 3 lanes
    }
}

__global__ __launch_bounds__(256, 6)
void plen_pass1(const float* __restrict__ dens,
                const float* __restrict__ sh,
                const float* __restrict__ rayo,
                const float* __restrict__ rayd,
                const int*   __restrict__ nsamp,
                int num_rays)
{
    __shared__ float s_p[8][100];            // per-warp 3 channels x 32 q's (stride 33)

    const int lane = threadIdx.x & 31;
    const int wid  = threadIdx.x >> 5;

    const int S = nsamp ? *nsamp : 128;
    const float delta = (FAR_T - NEAR_T) / (float)max(S - 1, 1);
    const int L = (S + 3) >> 2;              // samples per quarter-task (32 when S=128)

    // Lane roles for the SH gather: lanes 0..26 -> coeff (c=lane/9, k=lane%9).
    const int  c        = lane / 9;
    const int  k        = lane - c * 9;
    const bool shlane   = (lane < 27);
    const bool headlane = shlane && (k == 0);
    const int  p8src    = shlane ? (c * 9 + 8) : 31;
    const float* shp    = sh + lane;
    float* sp  = s_p[wid];
    float* spc = sp + c * 33;

    const int ntask = num_rays << 2;

    for (;;) {
        // dynamic task fetch (lane 0 pulls, broadcast)
        unsigned int t = 0;
        if (lane == 0) t = atomicAdd(&g_counter, 1u);
        t = __shfl_sync(FULLMASK, t, 0);
        if (t >= (unsigned)ntask) break;
        const int task = (int)t;

        const int ray = task >> 2;
        const int q   = task & 3;
        const int s0  = q * L;
        const int len = min(S, s0 + L) - s0;

        const float ox = __ldg(rayo + ray * 3 + 0);
        const float oy = __ldg(rayo + ray * 3 + 1);
        const float oz = __ldg(rayo + ray * 3 + 2);
        const float dx = __ldg(rayd + ray * 3 + 0);
        const float dy = __ldg(rayd + ray * 3 + 1);
        const float dz = __ldg(rayd + ray * 3 + 2);

        // degree-2 SH basis value for this lane's k, pre-scaled by -log2(e)
        float nx = dx, ny = dy, nz = dz;
        float ssq = nx * nx + ny * ny + nz * nz;
        if (ssq < 1e-8f) { nx = 0.0f; ny = 0.0f; nz = 1.0f; ssq = 1.0f; }
        const float invn = rsqrtf(ssq);
        nx *= invn; ny *= invn; nz *= invn;
        float bk;
        switch (k) {
            case 0:  bk = 0.282095f; break;
            case 1:  bk = 0.488603f * ny; break;
            case 2:  bk = 0.488603f * nz; break;
            case 3:  bk = 0.488603f * nx; break;
            case 4:  bk = 1.092548f * nx * ny; break;
            case 5:  bk = 1.092548f * ny * nz; break;
            case 6:  bk = 0.315392f * (3.0f * nz * nz - 1.0f); break;
            case 7:  bk = 1.092548f * nx * nz; break;
            default: bk = 0.546274f * (nx * nx - ny * ny); break;
        }
        bk *= -LOG2E;

        // voxel position p(s) = base + s*step  (scene [-1,1]^3, dims=127 -> *63.5)
        const float bx  = fmaf(NEAR_T * 63.5f, dx, (ox + 1.0f) * 63.5f);
        const float by  = fmaf(NEAR_T * 63.5f, dy, (oy + 1.0f) * 63.5f);
        const float bz  = fmaf(NEAR_T * 63.5f, dz, (oz + 1.0f) * 63.5f);
        const float stx = dx * (63.5f * delta);
        const float sty = dy * (63.5f * delta);
        const float stz = dz * (63.5f * delta);

        // ---- per-lane coordinate precompute: lane l owns sample s0+l ----
        const float sfl = (float)(s0 + lane);
        const float px = fmaf(sfl, stx, bx);
        const float py = fmaf(sfl, sty, by);
        const float pz = fmaf(sfl, stz, bz);
        const float pcx = fminf(fmaxf(px, 0.0f), 127.0f);
        const float pcy = fminf(fmaxf(py, 0.0f), 127.0f);
        const float pcz = fminf(fmaxf(pz, 0.0f), 127.0f);
        const float fxq = floorf(pcx), fyq = floorf(pcy), fzq = floorf(pcz);
        const float frxl = pcx - fxq, fryl = pcy - fyq, frzl = pcz - fzq;
        const int ix0 = (int)fxq, iy0 = (int)fyq, iz0 = (int)fzq;
        // frac==0 => +corner is multiplicatively dead => collapse its address
        const int dxb = (frxl > 0.0f) ? 1 : 0;
        const int dyb = (fryl > 0.0f) ? 1 : 0;
        const int dzb = (frzl > 0.0f) ? 1 : 0;
        const int a00l  = (ix0 << 14) + (iy0 << 7) + iz0;
        // pack a00*27 (< 2^26) + axis flags into one broadcast word
        const int codel = a00l * 27 | (dzb << 26) | (dyb << 27) | (dxb << 28);

        // ---- per-lane density trilerp for own sample (amortized over 32) ----
        const int Od  = a00l;
        const int DzD = dzb;
        const int DyD = dyb << 7;
        const int DxD = dxb << 14;
        const int OyD  = Od + DyD;
        const int OxD  = Od + DxD;
        const int OxyD = OxD + DyD;
        const float d000 = __ldg(dens + Od);
        const float d001 = __ldg(dens + Od  + DzD);
        const float d010 = __ldg(dens + OyD);
        const float d011 = __ldg(dens + OyD + DzD);
        const float d100 = __ldg(dens + OxD);
        const float d101 = __ldg(dens + OxD + DzD);
        const float d110 = __ldg(dens + OxyD);
        const float d111 = __ldg(dens + OxyD + DzD);
        const float z00d = fmaf(frzl, d001 - d000, d000);
        const float z01d = fmaf(frzl, d011 - d010, d010);
        const float z10d = fmaf(frzl, d101 - d100, d100);
        const float z11d = fmaf(frzl, d111 - d110, d110);
        const float y0d  = fmaf(fryl, z01d - z00d, z00d);
        const float y1d  = fmaf(fryl, z11d - z10d, z10d);
        float sig = fmaf(frxl, y1d - y0d, y0d);
        sig = fmaxf(sig, 0.0f);
        const float am1 = __expf(-sig * delta);       // 1 - alpha
        // inclusive scan-product of v = (1-alpha+1e-10) across lanes
        float P = am1 + 1e-10f;
        #pragma unroll
        for (int off = 1; off < 32; off <<= 1) {
            const float tprev = __shfl_up_sync(FULLMASK, P, off);
            if (lane >= off) P *= tprev;
        }
        float Tj = __shfl_up_sync(FULLMASK, P, 1);    // exclusive transmittance
        if (lane == 0) Tj = 1.0f;
        const float wlane = Tj * (1.0f - am1);        // this lane's sample weight
        const float Tout  = __shfl_sync(FULLMASK, P, len - 1);

        // ---- task-level axis-activity vote (only lanes owning real samples) ----
        const bool valid = lane < len;
        const unsigned bxv = __ballot_sync(FULLMASK, dxb && valid);
        const unsigned byv = __ballot_sync(FULLMASK, dyb && valid);
        const unsigned bzv = __ballot_sync(FULLMASK, dzb && valid);
        const int m = ((bxv ? 4 : 0) | (byv ? 2 : 0) | (bzv ? 1 : 0));

        switch (m) {
            case 0: run_quarter<false,false,false>(shp, shlane, headlane, p8src, bk, len, codel, frxl, fryl, frzl, spc); break;
            case 1: run_quarter<false,false,true >(shp, shlane, headlane, p8src, bk, len, codel, frxl, fryl, frzl, spc); break;
            case 2: run_quarter<false,true ,false>(shp, shlane, headlane, p8src, bk, len, codel, frxl, fryl, frzl, spc); break;
            case 3: run_quarter<false,true ,true >(shp, shlane, headlane, p8src, bk, len, codel, frxl, fryl, frzl, spc); break;
            case 4: run_quarter<true ,false,false>(shp, shlane, headlane, p8src, bk, len, codel, frxl, fryl, frzl, spc); break;
            case 5: run_quarter<true ,false,true >(shp, shlane, headlane, p8src, bk, len, codel, frxl, fryl, frzl, spc); break;
            case 6: run_quarter<true ,true ,false>(shp, shlane, headlane, p8src, bk, len, codel, frxl, fryl, frzl, spc); break;
            default:run_quarter<true ,true ,true >(shp, shlane, headlane, p8src, bk, len, codel, frxl, fryl, frzl, spc); break;
        }

        // ---- per-task tail: sigmoid + weight + sample-sum (parallel over lanes) ----
        __syncwarp();                                  // STS -> LDS visibility
        float q0 = sp[lane];
        float q1 = sp[33 + lane];
        float q2 = sp[66 + lane];
        __syncwarp();                                  // reads done before next task's STS
        if (!valid) { q0 = 0.0f; q1 = 0.0f; q2 = 0.0f; }
        const float wv = valid ? wlane : 0.0f;
        float r0 = wv * rcp_approx(1.0f + ex2_approx(q0));
        float r1 = wv * rcp_approx(1.0f + ex2_approx(q1));
        float r2 = wv * rcp_approx(1.0f + ex2_approx(q2));
        #pragma unroll
        for (int off = 16; off > 0; off >>= 1) {
            r0 += __shfl_xor_sync(FULLMASK, r0, off);
            r1 += __shfl_xor_sync(FULLMASK, r1, off);
            r2 += __shfl_xor_sync(FULLMASK, r2, off);
        }

        // emit quarter partials: one STG.128 {r,g,b,T} from lane 0
        if (lane == 0) {
            *(float4*)(g_partial + (task << 2)) = make_float4(r0, r1, r2, Tout);
        }
    }
}

__global__ __launch_bounds__(64)
void plen_pass2(float* __restrict__ out, int num_rays)
{
    const int r = blockIdx.x * blockDim.x + threadIdx.x;
    // reset the dynamic task counter for the next graph replay
    if (r == 0) g_counter = 0;
    if (r >= num_rays) return;
    const float4* p4 = (const float4*)(g_partial + (r << 4));
    const float4 q0 = p4[0], q1 = p4[1], q2 = p4[2], q3 = p4[3];
    float T = 1.0f, o0 = 0.0f, o1 = 0.0f, o2 = 0.0f;
    o0 = fmaf(T, q0.x, o0); o1 = fmaf(T, q0.y, o1); o2 = fmaf(T, q0.z, o2); T *= q0.w;
    o0 = fmaf(T, q1.x, o0); o1 = fmaf(T, q1.y, o1); o2 = fmaf(T, q1.z, o2); T *= q1.w;
    o0 = fmaf(T, q2.x, o0); o1 = fmaf(T, q2.y, o1); o2 = fmaf(T, q2.z, o2); T *= q2.w;
    o0 = fmaf(T, q3.x, o0); o1 = fmaf(T, q3.y, o1); o2 = fmaf(T, q3.z, o2); T *= q3.w;
    out[r * 3 + 0] = o0;
    out[r * 3 + 1] = o1;
    out[r * 3 + 2] = o2;
}

extern "C" void kernel_launch(void* const* d_in, const int* in_sizes, int n_in,
                              void* d_out, int out_size)
{
    const float* dens = (const float*)d_in[0];
    const float* sh   = (const float*)d_in[1];
    const float* ro   = (const float*)d_in[2];
    const float* rd   = (const float*)d_in[3];
    const int*   ns   = (n_in >= 5) ? (const int*)d_in[4] : nullptr;
    float* out = (float*)d_out;

    const int num_rays = in_sizes[2] / 3;

    const int grid1 = 888;   // 148 SMs x 6 CTAs of 256 -> 48 warps/SM, persistent
    plen_pass1<<<grid1, 256>>>(dens, sh, ro, rd, ns, num_rays);
    plen_pass2<<<(num_rays + 63) / 64, 64>>>(out, num_rays);
}